// round 13
// baseline (speedup 1.0000x reference)
#include <cuda_runtime.h>
#include <cub/cub.cuh>

#define BB 8
#define NN 2048
#define MM 2048
#define DIN 256
#define EE 128
#define LALPHA 0.01f
#define NCHUNK 128
#define CHUNK 16            // MM / NCHUNK

#define GEMM_BLOCKS 256
#define ATT1_BLOCKS 2048    // B*N / 8 rows-per-block
#define RP_ROWS 16          // rows per probs/ctx block
#define PROB_BLOCKS 1024    // BB*NN / RP_ROWS
#define SCAN_BLOCKS 256     // BB*NCHUNK / 4 chunks-per-block

// ---------------- scratch (device globals; no allocation allowed) ----------------
__device__ float g_v1[DIN];
__device__ float g_att2[BB * MM];
__device__ float g_E1p[BB * NN], g_E1n[BB * NN], g_key[BB * NN];   // key = -att1
__device__ float g_F2p[BB * MM], g_F2n[BB * MM];
__device__ float g_Wh2[BB * MM * EE];
__device__ float g_sortv[BB * MM];
__device__ int   g_sortidx[BB * MM];
__device__ float g_chP[BB * NCHUNK * EE], g_chN[BB * NCHUNK * EE];   // chunk totals
__device__ float g_offP[BB * (NCHUNK + 1) * EE], g_offN[BB * (NCHUNK + 1) * EE];
__device__ float g_sufP[BB * (MM + 1) * EE];   // chunk-LOCAL suffix of F2p*Wh2 (sorted)
__device__ float g_preN[BB * (MM + 1) * EE];   // chunk-LOCAL prefix of F2n*Wh2 (sorted)
__device__ float g_sufPs[BB * (MM + 1)];       // GLOBAL scalar suffix of F2p (sorted)
__device__ float g_preNs[BB * (MM + 1)];       // GLOBAL scalar prefix of F2n (sorted)
__device__ int   g_lo[BB * NN];
__device__ float g_c1[BB * NN], g_c2[BB * NN];

// ---------------- 1. v1 = W1 @ a1_top ----------------
__global__ void k_v(const float* __restrict__ W1, const float* __restrict__ a1) {
    int d = threadIdx.x;   // 0..255
    float s1 = 0.f;
    #pragma unroll 8
    for (int e = 0; e < EE; e++) s1 += W1[d * EE + e] * a1[e];
    g_v1[d] = s1;
}

// ---------------- 2. Wh2 GEMM via fma.f32x2 (blocks 0..255) + att1 (256..2303) -------
__global__ void __launch_bounds__(256) k_wh2(const float* __restrict__ in2,
                                             const float* __restrict__ W1,
                                             const float* __restrict__ mask,
                                             const float* __restrict__ a1,
                                             const float* __restrict__ in1) {
    __shared__ float As[64 * 32];
    __shared__ float Bs[32 * 128];
    int tid = threadIdx.x;

    if (blockIdx.x >= GEMM_BLOCKS) {
        // ---- att1 path: 8 warps, one row each ----
        int w    = (blockIdx.x - GEMM_BLOCKS) * 8 + (tid >> 5);   // 0 .. B*N-1
        int lane = tid & 31;
        const float4* p  = (const float4*)(in1 + (size_t)w * DIN);
        const float4* v4 = (const float4*)g_v1;
        float acc = 0.f;
        #pragma unroll
        for (int i = 0; i < 2; i++) {
            float4 x  = p[lane + 32 * i];
            float4 vv = v4[lane + 32 * i];
            acc += x.x * vv.x + x.y * vv.y + x.z * vv.z + x.w * vv.w;
        }
        #pragma unroll
        for (int o = 16; o > 0; o >>= 1) acc += __shfl_xor_sync(0xffffffffu, acc, o);
        if (lane == 0) {
            g_E1p[w] = expf(acc);
            g_E1n[w] = expf(LALPHA * acc);
            g_key[w] = -acc;
        }
        return;
    }

    // ---- GEMM path: 64 rows x 128 cols, K=256, packed f32x2 accumulators ----
    int tx = tid & 31;
    int ty = tid >> 5;
    int row0 = blockIdx.x * 64;
    uint64_t acc01[8], acc23[8];
    #pragma unroll
    for (int r = 0; r < 8; r++) { acc01[r] = 0ull; acc23[r] = 0ull; }

    for (int k0 = 0; k0 < DIN; k0 += 32) {
        #pragma unroll
        for (int i = tid; i < 512; i += 256) {
            int r = i >> 3, kq = i & 7;
            ((float4*)As)[i] = *(const float4*)(in2 + (size_t)(row0 + r) * DIN + k0 + kq * 4);
        }
        #pragma unroll
        for (int i = tid; i < 1024; i += 256) {
            ((float4*)Bs)[i] = ((const float4*)(W1 + (size_t)k0 * EE))[i];
        }
        __syncthreads();
        const uint64_t* Bs64 = (const uint64_t*)Bs;
        #pragma unroll
        for (int kk = 0; kk < 32; kk += 4) {
            uint64_t b01[4], b23[4];
            #pragma unroll
            for (int q = 0; q < 4; q++) {
                b01[q] = Bs64[(kk + q) * 64 + tx * 2 + 0];
                b23[q] = Bs64[(kk + q) * 64 + tx * 2 + 1];
            }
            #pragma unroll
            for (int r = 0; r < 8; r++) {
                float4 a4 = *(float4*)&As[(ty * 8 + r) * 32 + kk];
                uint64_t aa;
                asm("mov.b64 %0, {%1, %1};" : "=l"(aa) : "f"(a4.x));
                asm("fma.rn.f32x2 %0, %1, %2, %0;" : "+l"(acc01[r]) : "l"(aa), "l"(b01[0]));
                asm("fma.rn.f32x2 %0, %1, %2, %0;" : "+l"(acc23[r]) : "l"(aa), "l"(b23[0]));
                asm("mov.b64 %0, {%1, %1};" : "=l"(aa) : "f"(a4.y));
                asm("fma.rn.f32x2 %0, %1, %2, %0;" : "+l"(acc01[r]) : "l"(aa), "l"(b01[1]));
                asm("fma.rn.f32x2 %0, %1, %2, %0;" : "+l"(acc23[r]) : "l"(aa), "l"(b23[1]));
                asm("mov.b64 %0, {%1, %1};" : "=l"(aa) : "f"(a4.z));
                asm("fma.rn.f32x2 %0, %1, %2, %0;" : "+l"(acc01[r]) : "l"(aa), "l"(b01[2]));
                asm("fma.rn.f32x2 %0, %1, %2, %0;" : "+l"(acc23[r]) : "l"(aa), "l"(b23[2]));
                asm("mov.b64 %0, {%1, %1};" : "=l"(aa) : "f"(a4.w));
                asm("fma.rn.f32x2 %0, %1, %2, %0;" : "+l"(acc01[r]) : "l"(aa), "l"(b01[3]));
                asm("fma.rn.f32x2 %0, %1, %2, %0;" : "+l"(acc23[r]) : "l"(aa), "l"(b23[3]));
            }
        }
        __syncthreads();
    }
    float4 va = *(const float4*)(a1 + EE + tx * 4);
    #pragma unroll
    for (int r = 0; r < 8; r++) {
        float c0, c1, c2, c3;
        asm("mov.b64 {%0, %1}, %2;" : "=f"(c0), "=f"(c1) : "l"(acc01[r]));
        asm("mov.b64 {%0, %1}, %2;" : "=f"(c2), "=f"(c3) : "l"(acc23[r]));
        int row = row0 + ty * 8 + r;
        *(float4*)(g_Wh2 + (size_t)row * EE + tx * 4) = make_float4(c0, c1, c2, c3);
        float part = c0 * va.x + c1 * va.y + c2 * va.z + c3 * va.w;
        #pragma unroll
        for (int o = 16; o > 0; o >>= 1) part += __shfl_xor_sync(0xffffffffu, part, o);
        if (tx == 0) {
            int b = row >> 11, m = row & (MM - 1);
            float mk = mask[b * MM + m];
            g_att2[row] = part;
            g_F2p[row] = expf(part + mk);
            g_F2n[row] = expf(LALPHA * part + mk);
        }
    }
}

// ---------------- 3. per-batch radix sort + GLOBAL scalar scans ----------------
__global__ void __launch_bounds__(1024) k_sort() {
    typedef cub::BlockRadixSort<float, 1024, 2, int> Sorter;
    typedef cub::BlockScan<float, 1024> Scan;
    __shared__ union { typename Sorter::TempStorage sort;
                       typename Scan::TempStorage   scan; } tmp;
    __shared__ float sv[MM];
    int b = blockIdx.x;
    int t = threadIdx.x;
    float key[2];
    int   val[2];
    #pragma unroll
    for (int i = 0; i < 2; i++) {
        int idx = t * 2 + i;
        key[i] = g_att2[b * MM + idx];
        val[i] = idx;
    }
    Sorter(tmp.sort).Sort(key, val);
    g_sortv[b * MM + 2 * t]     = key[0];
    g_sortv[b * MM + 2 * t + 1] = key[1];
    g_sortidx[b * MM + 2 * t]     = val[0];
    g_sortidx[b * MM + 2 * t + 1] = val[1];
    float fp0 = g_F2p[b * MM + val[0]], fp1 = g_F2p[b * MM + val[1]];
    float fn0 = g_F2n[b * MM + val[0]], fn1 = g_F2n[b * MM + val[1]];

    // forward exclusive prefix of F2n (sorted order)
    float pre, tot;
    __syncthreads();
    Scan(tmp.scan).ExclusiveSum(fn0 + fn1, pre, tot);
    g_preNs[b * (MM + 1) + 2 * t]     = pre;
    g_preNs[b * (MM + 1) + 2 * t + 1] = pre + fn0;
    if (t == 0) g_preNs[b * (MM + 1) + MM] = tot;

    // direct suffix (inclusive) of F2p via reversed-order prefix
    sv[2 * t] = fp0;
    sv[2 * t + 1] = fp1;
    __syncthreads();
    float r0 = sv[MM - 1 - 2 * t];   // fp at k = MM-1-2t
    float r1 = sv[MM - 2 - 2 * t];   // fp at k = MM-2-2t
    float pre2;
    __syncthreads();
    Scan(tmp.scan).ExclusiveSum(r0 + r1, pre2);
    g_sufPs[b * (MM + 1) + (MM - 1 - 2 * t)] = pre2 + r0;
    g_sufPs[b * (MM + 1) + (MM - 2 - 2 * t)] = pre2 + r0 + r1;
    if (t == 0) g_sufPs[b * (MM + 1) + MM] = 0.f;
}

// ---------------- 4. fused: probs blocks (0..1023) || vector-scan blocks (1024..1279)
__global__ void __launch_bounds__(512) k_scanprobs(float* __restrict__ out_p) {
    __shared__ float sw[4][CHUNK][EE];
    __shared__ float sfp[4][CHUNK], sfn[4][CHUNK];
    __shared__ int   smi[4][CHUNK];
    __shared__ float sc1[RP_ROWS], sc2[RP_ROWS], skey[RP_ROWS];
    int tid = threadIdx.x;

    if (blockIdx.x < PROB_BLOCKS) {
        // ---- probs path (independent of vector scans) ----
        int g = blockIdx.x;
        int row0 = g * RP_ROWS;
        int b = row0 >> 11;
        if (tid < RP_ROWS) {
            int row = row0 + tid;
            float key = g_key[row];
            const float* sv = g_sortv + b * MM;
            int lo = 0, hi = MM;
            while (lo < hi) {
                int mid = (lo + hi) >> 1;
                if (sv[mid] > key) hi = mid; else lo = mid + 1;
            }
            float E1p = g_E1p[row], E1n = g_E1n[row];
            float S = E1p * g_sufPs[b * (MM + 1) + lo] + E1n * g_preNs[b * (MM + 1) + lo];
            float invS = 1.f / S;
            float c1v = E1p * invS, c2v = E1n * invS;
            sc1[tid] = c1v; sc2[tid] = c2v; skey[tid] = key;
            g_lo[row] = lo; g_c1[row] = c1v; g_c2[row] = c2v;
        }
        __syncthreads();
        const float4 tv = ((const float4*)(g_att2 + b * MM))[tid];
        const float4 pv = ((const float4*)(g_F2p + b * MM))[tid];
        const float4 nv = ((const float4*)(g_F2n + b * MM))[tid];
        #pragma unroll
        for (int r = 0; r < RP_ROWS; r++) {
            int row = row0 + r;
            float key = skey[r], c1 = sc1[r], c2 = sc2[r];
            float4 o;
            o.x = (tv.x > key) ? c1 * pv.x : c2 * nv.x;
            o.y = (tv.y > key) ? c1 * pv.y : c2 * nv.y;
            o.z = (tv.z > key) ? c1 * pv.z : c2 * nv.z;
            o.w = (tv.w > key) ? c1 * pv.w : c2 * nv.w;
            __stcs((float4*)(out_p + (size_t)row * MM) + tid, o);
        }
        return;
    }

    // ---- vector-scan path: 4 chunks per block ----
    int sid = blockIdx.x - PROB_BLOCKS;   // 0..255
    int b  = sid >> 5;                    // 32 groups per batch
    int cg = sid & 31;
    int sub = tid >> 7;                   // chunk within block, 0..3
    int e   = tid & 127;
    int c   = cg * 4 + sub;
    if (tid < 64) {
        int cc = tid >> 4, j = tid & 15;
        smi[cc][j] = g_sortidx[b * MM + (cg * 4 + cc) * CHUNK + j];
    }
    __syncthreads();
    #pragma unroll
    for (int i = tid; i < 4 * CHUNK * 32; i += 512) {
        int cc = i >> 9, row = (i >> 5) & 15, c4 = i & 31;
        ((float4*)&sw[cc][row][0])[c4] =
            ((const float4*)(g_Wh2 + (size_t)(b * MM + smi[cc][row]) * EE))[c4];
    }
    if (tid < 64) {
        int cc = tid >> 4, j = tid & 15;
        sfp[cc][j] = g_F2p[b * MM + smi[cc][j]];
        sfn[cc][j] = g_F2n[b * MM + smi[cc][j]];
    }
    __syncthreads();
    {
        float runN = 0.f;
        #pragma unroll
        for (int j = 0; j < CHUNK; j++) {
            g_preN[((size_t)b * (MM + 1) + c * CHUNK + j) * EE + e] = runN;
            runN += sfn[sub][j] * sw[sub][j][e];
        }
        g_chN[(b * NCHUNK + c) * EE + e] = runN;
    }
    {
        float runP = 0.f;
        #pragma unroll
        for (int j = CHUNK - 1; j >= 0; j--) {
            runP += sfp[sub][j] * sw[sub][j][e];
            g_sufP[((size_t)b * (MM + 1) + c * CHUNK + j) * EE + e] = runP;
        }
        g_chP[(b * NCHUNK + c) * EE + e] = runP;
    }
}

// ---------------- 5. chunk-level vector offsets (incl. sentinels) -------------------
__global__ void __launch_bounds__(EE) k_offsets() {
    int b = blockIdx.x, e = threadIdx.x;
    {
        float run = 0.f;
        for (int c = 0; c < NCHUNK; c += 8) {
            float v0 = g_chN[(b * NCHUNK + c + 0) * EE + e];
            float v1 = g_chN[(b * NCHUNK + c + 1) * EE + e];
            float v2 = g_chN[(b * NCHUNK + c + 2) * EE + e];
            float v3 = g_chN[(b * NCHUNK + c + 3) * EE + e];
            float v4 = g_chN[(b * NCHUNK + c + 4) * EE + e];
            float v5 = g_chN[(b * NCHUNK + c + 5) * EE + e];
            float v6 = g_chN[(b * NCHUNK + c + 6) * EE + e];
            float v7 = g_chN[(b * NCHUNK + c + 7) * EE + e];
            g_offN[(b * (NCHUNK + 1) + c + 0) * EE + e] = run;
            g_offN[(b * (NCHUNK + 1) + c + 1) * EE + e] = run + v0;
            g_offN[(b * (NCHUNK + 1) + c + 2) * EE + e] = run + v0 + v1;
            g_offN[(b * (NCHUNK + 1) + c + 3) * EE + e] = run + v0 + v1 + v2;
            float s4 = ((v0 + v1) + (v2 + v3));
            g_offN[(b * (NCHUNK + 1) + c + 4) * EE + e] = run + s4;
            g_offN[(b * (NCHUNK + 1) + c + 5) * EE + e] = run + s4 + v4;
            g_offN[(b * (NCHUNK + 1) + c + 6) * EE + e] = run + s4 + v4 + v5;
            g_offN[(b * (NCHUNK + 1) + c + 7) * EE + e] = run + s4 + v4 + v5 + v6;
            run += s4 + ((v4 + v5) + (v6 + v7));
        }
        g_offN[(b * (NCHUNK + 1) + NCHUNK) * EE + e] = run;
    }
    {
        float run = 0.f;
        g_offP[(b * (NCHUNK + 1) + NCHUNK) * EE + e] = 0.f;
        for (int c = NCHUNK - 8; c >= 0; c -= 8) {
            float v7 = g_chP[(b * NCHUNK + c + 7) * EE + e];
            float v6 = g_chP[(b * NCHUNK + c + 6) * EE + e];
            float v5 = g_chP[(b * NCHUNK + c + 5) * EE + e];
            float v4 = g_chP[(b * NCHUNK + c + 4) * EE + e];
            float v3 = g_chP[(b * NCHUNK + c + 3) * EE + e];
            float v2 = g_chP[(b * NCHUNK + c + 2) * EE + e];
            float v1 = g_chP[(b * NCHUNK + c + 1) * EE + e];
            float v0 = g_chP[(b * NCHUNK + c + 0) * EE + e];
            g_offP[(b * (NCHUNK + 1) + c + 7) * EE + e] = run;
            g_offP[(b * (NCHUNK + 1) + c + 6) * EE + e] = run + v7;
            g_offP[(b * (NCHUNK + 1) + c + 5) * EE + e] = run + v7 + v6;
            g_offP[(b * (NCHUNK + 1) + c + 4) * EE + e] = run + v7 + v6 + v5;
            float s4 = ((v7 + v6) + (v5 + v4));
            g_offP[(b * (NCHUNK + 1) + c + 3) * EE + e] = run + s4;
            g_offP[(b * (NCHUNK + 1) + c + 2) * EE + e] = run + s4 + v3;
            g_offP[(b * (NCHUNK + 1) + c + 1) * EE + e] = run + s4 + v3 + v2;
            g_offP[(b * (NCHUNK + 1) + c + 0) * EE + e] = run + s4 + v3 + v2 + v1;
            run += s4 + ((v3 + v2) + (v1 + v0));
        }
    }
    // zero local sentinels at k = MM
    g_preN[((size_t)b * (MM + 1) + MM) * EE + e] = 0.f;
    g_sufP[((size_t)b * (MM + 1) + MM) * EE + e] = 0.f;
}

// ---------------- 6. context from persisted lo/c1/c2 ----------------
__global__ void __launch_bounds__(512) k_ctx(float* __restrict__ out_ctx) {
    __shared__ int   slo[RP_ROWS];
    __shared__ float sc1[RP_ROWS], sc2[RP_ROWS];
    int g = blockIdx.x;
    int row0 = g * RP_ROWS;
    int b = row0 >> 11;
    int tid = threadIdx.x;
    if (tid < RP_ROWS) {
        slo[tid] = g_lo[row0 + tid];
        sc1[tid] = g_c1[row0 + tid];
        sc2[tid] = g_c2[row0 + tid];
    }
    __syncthreads();
    int e  = tid & (EE - 1);
    int rb = tid >> 7;
    #pragma unroll
    for (int it = 0; it < RP_ROWS / 4; it++) {
        int r = it * 4 + rb;
        int row = row0 + r;
        int k = slo[r], c = k >> 4;
        float sufP = g_sufP[((size_t)b * (MM + 1) + k) * EE + e]
                   + g_offP[(b * (NCHUNK + 1) + c) * EE + e];
        float preN = g_preN[((size_t)b * (MM + 1) + k) * EE + e]
                   + g_offN[(b * (NCHUNK + 1) + c) * EE + e];
        out_ctx[(size_t)row * EE + e] = sc1[r] * sufP + sc2[r] * preN;
    }
}

// ---------------- launch ----------------
extern "C" void kernel_launch(void* const* d_in, const int* in_sizes, int n_in,
                              void* d_out, int out_size) {
    const float* in1  = (const float*)d_in[0];   // (8,2048,256)
    const float* in2  = (const float*)d_in[1];   // (8,2048,256)
    const float* mask = (const float*)d_in[2];   // (8,1,2048)
    const float* W1   = (const float*)d_in[3];   // (256,128)
    const float* a1   = (const float*)d_in[4];   // (256,1)
    float* out = (float*)d_out;
    float* out_ctx   = out;                              // (8,2048,128)
    float* out_probs = out + (size_t)BB * NN * EE;       // (8,2048,2048)

    k_v<<<1, 256>>>(W1, a1);
    k_wh2<<<GEMM_BLOCKS + ATT1_BLOCKS, 256>>>(in2, W1, mask, a1, in1);
    k_sort<<<BB, 1024>>>();
    k_scanprobs<<<PROB_BLOCKS + SCAN_BLOCKS, 512>>>(out_probs);
    k_offsets<<<BB, EE>>>();
    k_ctx<<<BB * NN / RP_ROWS, 512>>>(out_ctx);
}

// round 15
// speedup vs baseline: 1.0374x; 1.0374x over previous
#include <cuda_runtime.h>
#include <cub/cub.cuh>

#define BB 8
#define NN 2048
#define MM 2048
#define DIN 256
#define EE 128
#define LALPHA 0.01f
#define NCHUNK 128
#define CHUNK 16            // MM / NCHUNK

#define GEMM_BLOCKS 256
#define ATT1_BLOCKS 2048    // B*N / 8 rows-per-block
#define RP_ROWS 16          // rows per probs/ctx block
#define SORT_BLOCKS 8
#define PROB_BLOCKS 1024    // BB*NN / RP_ROWS
#define SCAN_BLOCKS 256     // BB*NCHUNK / 4 chunks-per-block
#define MEGA_BLOCKS (SORT_BLOCKS + PROB_BLOCKS + SCAN_BLOCKS)

// ---------------- scratch (device globals; no allocation allowed) ----------------
__device__ float g_v1[DIN];
__device__ float g_att2[BB * MM];
__device__ float g_E1p[BB * NN], g_E1n[BB * NN], g_key[BB * NN];   // key = -att1
__device__ float g_F2p[BB * MM], g_F2n[BB * MM];
__device__ float g_Wh2[BB * MM * EE];
__device__ float g_sortv[BB * MM];
__device__ int   g_sortidx[BB * MM];
__device__ float g_chP[BB * NCHUNK * EE], g_chN[BB * NCHUNK * EE];   // chunk totals
__device__ float g_offP[BB * (NCHUNK + 1) * EE], g_offN[BB * (NCHUNK + 1) * EE];
__device__ float g_sufP[BB * (MM + 1) * EE];   // chunk-LOCAL suffix of F2p*Wh2 (sorted)
__device__ float g_preN[BB * (MM + 1) * EE];   // chunk-LOCAL prefix of F2n*Wh2 (sorted)
__device__ float g_c1[BB * NN], g_c2[BB * NN];
__device__ int   g_flag[BB];                   // sort-done flags (reset each replay)

// ---------------- 1. v1 = W1 @ a1_top (+ flag reset for this replay) ----------------
__global__ void k_v(const float* __restrict__ W1, const float* __restrict__ a1) {
    int d = threadIdx.x;   // 0..255
    if (d < BB) g_flag[d] = 0;
    float s1 = 0.f;
    #pragma unroll 8
    for (int e = 0; e < EE; e++) s1 += W1[d * EE + e] * a1[e];
    g_v1[d] = s1;
}

// ---------------- 2. Wh2 GEMM via fma.f32x2 (blocks 0..255) + att1 (256..2303) -------
__global__ void __launch_bounds__(256) k_wh2(const float* __restrict__ in2,
                                             const float* __restrict__ W1,
                                             const float* __restrict__ mask,
                                             const float* __restrict__ a1,
                                             const float* __restrict__ in1) {
    __shared__ float As[64 * 32];
    __shared__ float Bs[32 * 128];
    int tid = threadIdx.x;

    if (blockIdx.x >= GEMM_BLOCKS) {
        // ---- att1 path: 8 warps, one row each ----
        int w    = (blockIdx.x - GEMM_BLOCKS) * 8 + (tid >> 5);   // 0 .. B*N-1
        int lane = tid & 31;
        const float4* p  = (const float4*)(in1 + (size_t)w * DIN);
        const float4* v4 = (const float4*)g_v1;
        float acc = 0.f;
        #pragma unroll
        for (int i = 0; i < 2; i++) {
            float4 x  = p[lane + 32 * i];
            float4 vv = v4[lane + 32 * i];
            acc += x.x * vv.x + x.y * vv.y + x.z * vv.z + x.w * vv.w;
        }
        #pragma unroll
        for (int o = 16; o > 0; o >>= 1) acc += __shfl_xor_sync(0xffffffffu, acc, o);
        if (lane == 0) {
            g_E1p[w] = expf(acc);
            g_E1n[w] = expf(LALPHA * acc);
            g_key[w] = -acc;
        }
        return;
    }

    // ---- GEMM path: 64 rows x 128 cols, K=256, packed f32x2 accumulators ----
    int tx = tid & 31;
    int ty = tid >> 5;
    int row0 = blockIdx.x * 64;
    uint64_t acc01[8], acc23[8];
    #pragma unroll
    for (int r = 0; r < 8; r++) { acc01[r] = 0ull; acc23[r] = 0ull; }

    for (int k0 = 0; k0 < DIN; k0 += 32) {
        #pragma unroll
        for (int i = tid; i < 512; i += 256) {
            int r = i >> 3, kq = i & 7;
            ((float4*)As)[i] = *(const float4*)(in2 + (size_t)(row0 + r) * DIN + k0 + kq * 4);
        }
        #pragma unroll
        for (int i = tid; i < 1024; i += 256) {
            ((float4*)Bs)[i] = ((const float4*)(W1 + (size_t)k0 * EE))[i];
        }
        __syncthreads();
        const uint64_t* Bs64 = (const uint64_t*)Bs;
        #pragma unroll
        for (int kk = 0; kk < 32; kk += 4) {
            uint64_t b01[4], b23[4];
            #pragma unroll
            for (int q = 0; q < 4; q++) {
                b01[q] = Bs64[(kk + q) * 64 + tx * 2 + 0];
                b23[q] = Bs64[(kk + q) * 64 + tx * 2 + 1];
            }
            #pragma unroll
            for (int r = 0; r < 8; r++) {
                float4 a4 = *(float4*)&As[(ty * 8 + r) * 32 + kk];
                uint64_t aa;
                asm("mov.b64 %0, {%1, %1};" : "=l"(aa) : "f"(a4.x));
                asm("fma.rn.f32x2 %0, %1, %2, %0;" : "+l"(acc01[r]) : "l"(aa), "l"(b01[0]));
                asm("fma.rn.f32x2 %0, %1, %2, %0;" : "+l"(acc23[r]) : "l"(aa), "l"(b23[0]));
                asm("mov.b64 %0, {%1, %1};" : "=l"(aa) : "f"(a4.y));
                asm("fma.rn.f32x2 %0, %1, %2, %0;" : "+l"(acc01[r]) : "l"(aa), "l"(b01[1]));
                asm("fma.rn.f32x2 %0, %1, %2, %0;" : "+l"(acc23[r]) : "l"(aa), "l"(b23[1]));
                asm("mov.b64 %0, {%1, %1};" : "=l"(aa) : "f"(a4.z));
                asm("fma.rn.f32x2 %0, %1, %2, %0;" : "+l"(acc01[r]) : "l"(aa), "l"(b01[2]));
                asm("fma.rn.f32x2 %0, %1, %2, %0;" : "+l"(acc23[r]) : "l"(aa), "l"(b23[2]));
                asm("mov.b64 %0, {%1, %1};" : "=l"(aa) : "f"(a4.w));
                asm("fma.rn.f32x2 %0, %1, %2, %0;" : "+l"(acc01[r]) : "l"(aa), "l"(b01[3]));
                asm("fma.rn.f32x2 %0, %1, %2, %0;" : "+l"(acc23[r]) : "l"(aa), "l"(b23[3]));
            }
        }
        __syncthreads();
    }
    float4 va = *(const float4*)(a1 + EE + tx * 4);
    #pragma unroll
    for (int r = 0; r < 8; r++) {
        float c0, c1, c2, c3;
        asm("mov.b64 {%0, %1}, %2;" : "=f"(c0), "=f"(c1) : "l"(acc01[r]));
        asm("mov.b64 {%0, %1}, %2;" : "=f"(c2), "=f"(c3) : "l"(acc23[r]));
        int row = row0 + ty * 8 + r;
        *(float4*)(g_Wh2 + (size_t)row * EE + tx * 4) = make_float4(c0, c1, c2, c3);
        float part = c0 * va.x + c1 * va.y + c2 * va.z + c3 * va.w;
        #pragma unroll
        for (int o = 16; o > 0; o >>= 1) part += __shfl_xor_sync(0xffffffffu, part, o);
        if (tx == 0) {
            int b = row >> 11, m = row & (MM - 1);
            float mk = mask[b * MM + m];
            g_att2[row] = part;
            g_F2p[row] = expf(part + mk);
            g_F2n[row] = expf(LALPHA * part + mk);
        }
    }
}

// ---------------- 3. mega: sort (0..7) || probs+direct-S (8..1031) || scan (1032..1287)
__global__ void __launch_bounds__(512) k_mega(float* __restrict__ out_p) {
    typedef cub::BlockRadixSort<float, 512, 4, int> Sorter;
    __shared__ union {
        typename Sorter::TempStorage sort;
        float red[RP_ROWS * 512];                       // probs reduction (32 KB)
        struct {
            float sw[4][CHUNK][EE];
            float sfp[4][CHUNK], sfn[4][CHUNK];
            int   smi[4][CHUNK];
        } scan;
    } sh;
    __shared__ float skey[RP_ROWS], sc1[RP_ROWS], sc2[RP_ROWS], sSP[RP_ROWS];
    int tid = threadIdx.x;

    if (blockIdx.x < SORT_BLOCKS) {
        // ---- sort path: one batch per block ----
        int b = blockIdx.x;
        float key[4];
        int   val[4];
        #pragma unroll
        for (int i = 0; i < 4; i++) {
            int idx = tid * 4 + i;
            key[i] = g_att2[b * MM + idx];
            val[i] = idx;
        }
        Sorter(sh.sort).Sort(key, val);
        #pragma unroll
        for (int i = 0; i < 4; i++) {
            int idx = tid * 4 + i;
            g_sortv[b * MM + idx]   = key[i];
            g_sortidx[b * MM + idx] = val[i];
        }
        __syncthreads();
        __threadfence();
        if (tid == 0) atomicExch(&g_flag[b], 1);
        return;
    }

    if (blockIdx.x < SORT_BLOCKS + PROB_BLOCKS) {
        // ---- probs path with direct two-branch S (no sort dependency) ----
        int g = blockIdx.x - SORT_BLOCKS;
        int row0 = g * RP_ROWS;
        int b = row0 >> 11;
        if (tid < RP_ROWS) skey[tid] = g_key[row0 + tid];
        __syncthreads();
        const float4 tv = ((const float4*)(g_att2 + b * MM))[tid];
        const float4 pv = ((const float4*)(g_F2p + b * MM))[tid];
        const float4 nv = ((const float4*)(g_F2n + b * MM))[tid];
        // pass 1: positive-branch partials  sP = sum_{att2>key} F2p
        #pragma unroll
        for (int r = 0; r < RP_ROWS; r++) {
            float key = skey[r];
            float p = ((tv.x > key) ? pv.x : 0.f)
                    + ((tv.y > key) ? pv.y : 0.f)
                    + ((tv.z > key) ? pv.z : 0.f)
                    + ((tv.w > key) ? pv.w : 0.f);
            sh.red[r * 512 + tid] = p;
        }
        __syncthreads();
        {
            int w = tid >> 5, l = tid & 31;
            float s = 0.f;
            #pragma unroll
            for (int i = 0; i < 16; i++) s += sh.red[w * 512 + l + 32 * i];
            #pragma unroll
            for (int o = 16; o > 0; o >>= 1) s += __shfl_xor_sync(0xffffffffu, s, o);
            if (l == 0) sSP[w] = s;
        }
        __syncthreads();
        // pass 2: negative-branch partials  sN = sum_{att2<=key} F2n
        #pragma unroll
        for (int r = 0; r < RP_ROWS; r++) {
            float key = skey[r];
            float p = ((tv.x > key) ? 0.f : nv.x)
                    + ((tv.y > key) ? 0.f : nv.y)
                    + ((tv.z > key) ? 0.f : nv.z)
                    + ((tv.w > key) ? 0.f : nv.w);
            sh.red[r * 512 + tid] = p;
        }
        __syncthreads();
        {
            int w = tid >> 5, l = tid & 31;
            float s = 0.f;
            #pragma unroll
            for (int i = 0; i < 16; i++) s += sh.red[w * 512 + l + 32 * i];
            #pragma unroll
            for (int o = 16; o > 0; o >>= 1) s += __shfl_xor_sync(0xffffffffu, s, o);
            if (l == 0) {
                int row = row0 + w;
                float E1p = g_E1p[row], E1n = g_E1n[row];
                float S = E1p * sSP[w] + E1n * s;        // correct two-branch S
                float invS = 1.f / S;
                float c1v = E1p * invS, c2v = E1n * invS;
                sc1[w] = c1v; sc2[w] = c2v;
                g_c1[row] = c1v; g_c2[row] = c2v;
            }
        }
        __syncthreads();
        // probs stores (streaming)
        #pragma unroll
        for (int r = 0; r < RP_ROWS; r++) {
            int row = row0 + r;
            float key = skey[r], c1 = sc1[r], c2 = sc2[r];
            float4 o;
            o.x = (tv.x > key) ? c1 * pv.x : c2 * nv.x;
            o.y = (tv.y > key) ? c1 * pv.y : c2 * nv.y;
            o.z = (tv.z > key) ? c1 * pv.z : c2 * nv.z;
            o.w = (tv.w > key) ? c1 * pv.w : c2 * nv.w;
            __stcs((float4*)(out_p + (size_t)row * MM) + tid, o);
        }
        return;
    }

    // ---- vector-scan path: spin on sort flag, then 4 chunks per block ----
    int sid = blockIdx.x - (SORT_BLOCKS + PROB_BLOCKS);   // 0..255
    int b  = sid >> 5;
    int cg = sid & 31;
    int sub = tid >> 7;
    int e   = tid & 127;
    int c   = cg * 4 + sub;
    if (tid == 0) {
        while (((volatile int*)g_flag)[b] == 0) {}
    }
    __syncthreads();
    __threadfence();
    if (tid < 64) {
        int cc = tid >> 4, j = tid & 15;
        sh.scan.smi[cc][j] = g_sortidx[b * MM + (cg * 4 + cc) * CHUNK + j];
    }
    __syncthreads();
    #pragma unroll
    for (int i = tid; i < 4 * CHUNK * 32; i += 512) {
        int cc = i >> 9, row = (i >> 5) & 15, c4 = i & 31;
        ((float4*)&sh.scan.sw[cc][row][0])[c4] =
            ((const float4*)(g_Wh2 + (size_t)(b * MM + sh.scan.smi[cc][row]) * EE))[c4];
    }
    if (tid < 64) {
        int cc = tid >> 4, j = tid & 15;
        sh.scan.sfp[cc][j] = g_F2p[b * MM + sh.scan.smi[cc][j]];
        sh.scan.sfn[cc][j] = g_F2n[b * MM + sh.scan.smi[cc][j]];
    }
    __syncthreads();
    {
        float runN = 0.f;
        #pragma unroll
        for (int j = 0; j < CHUNK; j++) {
            g_preN[((size_t)b * (MM + 1) + c * CHUNK + j) * EE + e] = runN;
            runN += sh.scan.sfn[sub][j] * sh.scan.sw[sub][j][e];
        }
        g_chN[(b * NCHUNK + c) * EE + e] = runN;
    }
    {
        float runP = 0.f;
        #pragma unroll
        for (int j = CHUNK - 1; j >= 0; j--) {
            runP += sh.scan.sfp[sub][j] * sh.scan.sw[sub][j][e];
            g_sufP[((size_t)b * (MM + 1) + c * CHUNK + j) * EE + e] = runP;
        }
        g_chP[(b * NCHUNK + c) * EE + e] = runP;
    }
}

// ---------------- 4. chunk-level vector offsets (incl. sentinels) -------------------
__global__ void __launch_bounds__(EE) k_offsets() {
    int b = blockIdx.x, e = threadIdx.x;
    {
        float run = 0.f;
        for (int c = 0; c < NCHUNK; c += 8) {
            float v0 = g_chN[(b * NCHUNK + c + 0) * EE + e];
            float v1 = g_chN[(b * NCHUNK + c + 1) * EE + e];
            float v2 = g_chN[(b * NCHUNK + c + 2) * EE + e];
            float v3 = g_chN[(b * NCHUNK + c + 3) * EE + e];
            float v4 = g_chN[(b * NCHUNK + c + 4) * EE + e];
            float v5 = g_chN[(b * NCHUNK + c + 5) * EE + e];
            float v6 = g_chN[(b * NCHUNK + c + 6) * EE + e];
            float v7 = g_chN[(b * NCHUNK + c + 7) * EE + e];
            g_offN[(b * (NCHUNK + 1) + c + 0) * EE + e] = run;
            g_offN[(b * (NCHUNK + 1) + c + 1) * EE + e] = run + v0;
            g_offN[(b * (NCHUNK + 1) + c + 2) * EE + e] = run + v0 + v1;
            g_offN[(b * (NCHUNK + 1) + c + 3) * EE + e] = run + v0 + v1 + v2;
            float s4 = ((v0 + v1) + (v2 + v3));
            g_offN[(b * (NCHUNK + 1) + c + 4) * EE + e] = run + s4;
            g_offN[(b * (NCHUNK + 1) + c + 5) * EE + e] = run + s4 + v4;
            g_offN[(b * (NCHUNK + 1) + c + 6) * EE + e] = run + s4 + v4 + v5;
            g_offN[(b * (NCHUNK + 1) + c + 7) * EE + e] = run + s4 + v4 + v5 + v6;
            run += s4 + ((v4 + v5) + (v6 + v7));
        }
        g_offN[(b * (NCHUNK + 1) + NCHUNK) * EE + e] = run;
    }
    {
        float run = 0.f;
        g_offP[(b * (NCHUNK + 1) + NCHUNK) * EE + e] = 0.f;
        for (int c = NCHUNK - 8; c >= 0; c -= 8) {
            float v7 = g_chP[(b * NCHUNK + c + 7) * EE + e];
            float v6 = g_chP[(b * NCHUNK + c + 6) * EE + e];
            float v5 = g_chP[(b * NCHUNK + c + 5) * EE + e];
            float v4 = g_chP[(b * NCHUNK + c + 4) * EE + e];
            float v3 = g_chP[(b * NCHUNK + c + 3) * EE + e];
            float v2 = g_chP[(b * NCHUNK + c + 2) * EE + e];
            float v1 = g_chP[(b * NCHUNK + c + 1) * EE + e];
            float v0 = g_chP[(b * NCHUNK + c + 0) * EE + e];
            g_offP[(b * (NCHUNK + 1) + c + 7) * EE + e] = run;
            g_offP[(b * (NCHUNK + 1) + c + 6) * EE + e] = run + v7;
            g_offP[(b * (NCHUNK + 1) + c + 5) * EE + e] = run + v7 + v6;
            g_offP[(b * (NCHUNK + 1) + c + 4) * EE + e] = run + v7 + v6 + v5;
            float s4 = ((v7 + v6) + (v5 + v4));
            g_offP[(b * (NCHUNK + 1) + c + 3) * EE + e] = run + s4;
            g_offP[(b * (NCHUNK + 1) + c + 2) * EE + e] = run + s4 + v3;
            g_offP[(b * (NCHUNK + 1) + c + 1) * EE + e] = run + s4 + v3 + v2;
            g_offP[(b * (NCHUNK + 1) + c + 0) * EE + e] = run + s4 + v3 + v2 + v1;
            run += s4 + ((v3 + v2) + (v1 + v0));
        }
    }
    // zero local sentinels at k = MM
    g_preN[((size_t)b * (MM + 1) + MM) * EE + e] = 0.f;
    g_sufP[((size_t)b * (MM + 1) + MM) * EE + e] = 0.f;
}

// ---------------- 5. context: binary search + compose local+offset vectors ----------
__global__ void __launch_bounds__(512) k_ctx(float* __restrict__ out_ctx) {
    __shared__ int   slo[RP_ROWS];
    __shared__ float sc1[RP_ROWS], sc2[RP_ROWS];
    int g = blockIdx.x;
    int row0 = g * RP_ROWS;
    int b = row0 >> 11;
    int tid = threadIdx.x;
    if (tid < RP_ROWS) {
        int row = row0 + tid;
        float key = g_key[row];
        const float* sv = g_sortv + b * MM;
        int lo = 0, hi = MM;
        while (lo < hi) {
            int mid = (lo + hi) >> 1;
            if (sv[mid] > key) hi = mid; else lo = mid + 1;
        }
        slo[tid] = lo;
        sc1[tid] = g_c1[row];
        sc2[tid] = g_c2[row];
    }
    __syncthreads();
    int e  = tid & (EE - 1);
    int rb = tid >> 7;
    #pragma unroll
    for (int it = 0; it < RP_ROWS / 4; it++) {
        int r = it * 4 + rb;
        int row = row0 + r;
        int k = slo[r], c = k >> 4;
        float sufP = g_sufP[((size_t)b * (MM + 1) + k) * EE + e]
                   + g_offP[(b * (NCHUNK + 1) + c) * EE + e];
        float preN = g_preN[((size_t)b * (MM + 1) + k) * EE + e]
                   + g_offN[(b * (NCHUNK + 1) + c) * EE + e];
        out_ctx[(size_t)row * EE + e] = sc1[r] * sufP + sc2[r] * preN;
    }
}

// ---------------- launch ----------------
extern "C" void kernel_launch(void* const* d_in, const int* in_sizes, int n_in,
                              void* d_out, int out_size) {
    const float* in1  = (const float*)d_in[0];   // (8,2048,256)
    const float* in2  = (const float*)d_in[1];   // (8,2048,256)
    const float* mask = (const float*)d_in[2];   // (8,1,2048)
    const float* W1   = (const float*)d_in[3];   // (256,128)
    const float* a1   = (const float*)d_in[4];   // (256,1)
    float* out = (float*)d_out;
    float* out_ctx   = out;                              // (8,2048,128)
    float* out_probs = out + (size_t)BB * NN * EE;       // (8,2048,2048)

    k_v<<<1, 256>>>(W1, a1);                             // also resets g_flag
    k_wh2<<<GEMM_BLOCKS + ATT1_BLOCKS, 256>>>(in2, W1, mask, a1, in1);
    k_mega<<<MEGA_BLOCKS, 512>>>(out_probs);
    k_offsets<<<BB, EE>>>();
    k_ctx<<<BB * NN / RP_ROWS, 512>>>(out_ctx);
}

// round 16
// speedup vs baseline: 1.1174x; 1.0772x over previous
#include <cuda_runtime.h>
#include <cub/cub.cuh>

#define BB 8
#define NN 2048
#define MM 2048
#define DIN 256
#define EE 128
#define LALPHA 0.01f
#define NCHUNK 128
#define CHUNK 16            // MM / NCHUNK

#define GEMM_BLOCKS 256
#define ATT1_BLOCKS 2048    // B*N / 8 rows-per-block
#define RP_ROWS 16          // rows per probs/ctx block
#define SORT_BLOCKS 8
#define PROB_BLOCKS 1024    // BB*NN / RP_ROWS
#define SCAN_BLOCKS 256     // BB*NCHUNK / 4 chunks-per-block
#define MEGA_BLOCKS (SORT_BLOCKS + PROB_BLOCKS + SCAN_BLOCKS)

// ---------------- scratch (device globals; no allocation allowed) ----------------
__device__ float g_v1[DIN];
__device__ float g_att2[BB * MM];
__device__ float g_E1p[BB * NN], g_E1n[BB * NN], g_key[BB * NN];   // key = -att1
__device__ float g_F2p[BB * MM], g_F2n[BB * MM];
__device__ float g_Wh2[BB * MM * EE];
__device__ float g_sortv[BB * MM];
__device__ int   g_sortidx[BB * MM];
__device__ float g_chP[BB * NCHUNK * EE], g_chN[BB * NCHUNK * EE];   // chunk totals
__device__ float g_offP[BB * (NCHUNK + 1) * EE], g_offN[BB * (NCHUNK + 1) * EE];
__device__ float g_sufP[BB * (MM + 1) * EE];   // chunk-LOCAL suffix of F2p*Wh2 (sorted)
__device__ float g_preN[BB * (MM + 1) * EE];   // chunk-LOCAL prefix of F2n*Wh2 (sorted)
__device__ float g_c1[BB * NN], g_c2[BB * NN];
__device__ int   g_flag[BB];                   // sort-done flags (reset each replay)

// ---------------- 1. v1 = W1 @ a1_top (+ flag reset for this replay) ----------------
__global__ void k_v(const float* __restrict__ W1, const float* __restrict__ a1) {
    int d = threadIdx.x;   // 0..255
    if (d < BB) g_flag[d] = 0;
    float s1 = 0.f;
    #pragma unroll 8
    for (int e = 0; e < EE; e++) s1 += W1[d * EE + e] * a1[e];
    g_v1[d] = s1;
}

// ---------------- 2. Wh2 GEMM via fma.f32x2 (blocks 0..255) + att1 (256..2303) -------
__global__ void __launch_bounds__(256) k_wh2(const float* __restrict__ in2,
                                             const float* __restrict__ W1,
                                             const float* __restrict__ mask,
                                             const float* __restrict__ a1,
                                             const float* __restrict__ in1) {
    __shared__ float As[64 * 32];
    __shared__ float Bs[32 * 128];
    int tid = threadIdx.x;

    if (blockIdx.x >= GEMM_BLOCKS) {
        // ---- att1 path: 8 warps, one row each ----
        int w    = (blockIdx.x - GEMM_BLOCKS) * 8 + (tid >> 5);   // 0 .. B*N-1
        int lane = tid & 31;
        const float4* p  = (const float4*)(in1 + (size_t)w * DIN);
        const float4* v4 = (const float4*)g_v1;
        float acc = 0.f;
        #pragma unroll
        for (int i = 0; i < 2; i++) {
            float4 x  = p[lane + 32 * i];
            float4 vv = v4[lane + 32 * i];
            acc += x.x * vv.x + x.y * vv.y + x.z * vv.z + x.w * vv.w;
        }
        #pragma unroll
        for (int o = 16; o > 0; o >>= 1) acc += __shfl_xor_sync(0xffffffffu, acc, o);
        if (lane == 0) {
            g_E1p[w] = expf(acc);
            g_E1n[w] = expf(LALPHA * acc);
            g_key[w] = -acc;
        }
        return;
    }

    // ---- GEMM path: 64 rows x 128 cols, K=256, packed f32x2 accumulators ----
    int tx = tid & 31;
    int ty = tid >> 5;
    int row0 = blockIdx.x * 64;
    uint64_t acc01[8], acc23[8];
    #pragma unroll
    for (int r = 0; r < 8; r++) { acc01[r] = 0ull; acc23[r] = 0ull; }

    for (int k0 = 0; k0 < DIN; k0 += 32) {
        #pragma unroll
        for (int i = tid; i < 512; i += 256) {
            int r = i >> 3, kq = i & 7;
            ((float4*)As)[i] = *(const float4*)(in2 + (size_t)(row0 + r) * DIN + k0 + kq * 4);
        }
        #pragma unroll
        for (int i = tid; i < 1024; i += 256) {
            ((float4*)Bs)[i] = ((const float4*)(W1 + (size_t)k0 * EE))[i];
        }
        __syncthreads();
        const uint64_t* Bs64 = (const uint64_t*)Bs;
        #pragma unroll
        for (int kk = 0; kk < 32; kk += 4) {
            uint64_t b01[4], b23[4];
            #pragma unroll
            for (int q = 0; q < 4; q++) {
                b01[q] = Bs64[(kk + q) * 64 + tx * 2 + 0];
                b23[q] = Bs64[(kk + q) * 64 + tx * 2 + 1];
            }
            #pragma unroll
            for (int r = 0; r < 8; r++) {
                float4 a4 = *(float4*)&As[(ty * 8 + r) * 32 + kk];
                uint64_t aa;
                asm("mov.b64 %0, {%1, %1};" : "=l"(aa) : "f"(a4.x));
                asm("fma.rn.f32x2 %0, %1, %2, %0;" : "+l"(acc01[r]) : "l"(aa), "l"(b01[0]));
                asm("fma.rn.f32x2 %0, %1, %2, %0;" : "+l"(acc23[r]) : "l"(aa), "l"(b23[0]));
                asm("mov.b64 %0, {%1, %1};" : "=l"(aa) : "f"(a4.y));
                asm("fma.rn.f32x2 %0, %1, %2, %0;" : "+l"(acc01[r]) : "l"(aa), "l"(b01[1]));
                asm("fma.rn.f32x2 %0, %1, %2, %0;" : "+l"(acc23[r]) : "l"(aa), "l"(b23[1]));
                asm("mov.b64 %0, {%1, %1};" : "=l"(aa) : "f"(a4.z));
                asm("fma.rn.f32x2 %0, %1, %2, %0;" : "+l"(acc01[r]) : "l"(aa), "l"(b01[2]));
                asm("fma.rn.f32x2 %0, %1, %2, %0;" : "+l"(acc23[r]) : "l"(aa), "l"(b23[2]));
                asm("mov.b64 %0, {%1, %1};" : "=l"(aa) : "f"(a4.w));
                asm("fma.rn.f32x2 %0, %1, %2, %0;" : "+l"(acc01[r]) : "l"(aa), "l"(b01[3]));
                asm("fma.rn.f32x2 %0, %1, %2, %0;" : "+l"(acc23[r]) : "l"(aa), "l"(b23[3]));
            }
        }
        __syncthreads();
    }
    float4 va = *(const float4*)(a1 + EE + tx * 4);
    #pragma unroll
    for (int r = 0; r < 8; r++) {
        float c0, c1, c2, c3;
        asm("mov.b64 {%0, %1}, %2;" : "=f"(c0), "=f"(c1) : "l"(acc01[r]));
        asm("mov.b64 {%0, %1}, %2;" : "=f"(c2), "=f"(c3) : "l"(acc23[r]));
        int row = row0 + ty * 8 + r;
        *(float4*)(g_Wh2 + (size_t)row * EE + tx * 4) = make_float4(c0, c1, c2, c3);
        float part = c0 * va.x + c1 * va.y + c2 * va.z + c3 * va.w;
        #pragma unroll
        for (int o = 16; o > 0; o >>= 1) part += __shfl_xor_sync(0xffffffffu, part, o);
        if (tx == 0) {
            int b = row >> 11, m = row & (MM - 1);
            float mk = mask[b * MM + m];
            g_att2[row] = part;
            g_F2p[row] = expf(part + mk);
            g_F2n[row] = expf(LALPHA * part + mk);
        }
    }
}

// ---------------- 3. mega: sort (0..7) || probs+direct-S (8..1031) || scan (1032..1287)
__global__ void __launch_bounds__(512) k_mega(float* __restrict__ out_p) {
    typedef cub::BlockRadixSort<float, 512, 4, int> Sorter;
    __shared__ union {
        typename Sorter::TempStorage sort;
        float red[RP_ROWS * 512];                       // probs reduction (32 KB)
        struct {
            float sw[4][CHUNK][EE];
            float sfp[4][CHUNK], sfn[4][CHUNK];
            int   smi[4][CHUNK];
        } scan;
    } sh;
    __shared__ float skey[RP_ROWS], sc1[RP_ROWS], sc2[RP_ROWS], sSP[RP_ROWS];
    int tid = threadIdx.x;

    if (blockIdx.x < SORT_BLOCKS) {
        // ---- sort path: one batch per block ----
        int b = blockIdx.x;
        float key[4];
        int   val[4];
        #pragma unroll
        for (int i = 0; i < 4; i++) {
            int idx = tid * 4 + i;
            key[i] = g_att2[b * MM + idx];
            val[i] = idx;
        }
        Sorter(sh.sort).Sort(key, val);
        #pragma unroll
        for (int i = 0; i < 4; i++) {
            int idx = tid * 4 + i;
            g_sortv[b * MM + idx]   = key[i];
            g_sortidx[b * MM + idx] = val[i];
        }
        __syncthreads();
        __threadfence();
        if (tid == 0) atomicExch(&g_flag[b], 1);
        return;
    }

    if (blockIdx.x < SORT_BLOCKS + PROB_BLOCKS) {
        // ---- probs path with direct two-branch S (no sort dependency) ----
        int g = blockIdx.x - SORT_BLOCKS;
        int row0 = g * RP_ROWS;
        int b = row0 >> 11;
        if (tid < RP_ROWS) skey[tid] = g_key[row0 + tid];
        __syncthreads();
        const float4 tv = ((const float4*)(g_att2 + b * MM))[tid];
        const float4 pv = ((const float4*)(g_F2p + b * MM))[tid];
        const float4 nv = ((const float4*)(g_F2n + b * MM))[tid];
        // pass 1: positive-branch partials  sP = sum_{att2>key} F2p
        #pragma unroll
        for (int r = 0; r < RP_ROWS; r++) {
            float key = skey[r];
            float p = ((tv.x > key) ? pv.x : 0.f)
                    + ((tv.y > key) ? pv.y : 0.f)
                    + ((tv.z > key) ? pv.z : 0.f)
                    + ((tv.w > key) ? pv.w : 0.f);
            sh.red[r * 512 + tid] = p;
        }
        __syncthreads();
        {
            int w = tid >> 5, l = tid & 31;
            float s = 0.f;
            #pragma unroll
            for (int i = 0; i < 16; i++) s += sh.red[w * 512 + l + 32 * i];
            #pragma unroll
            for (int o = 16; o > 0; o >>= 1) s += __shfl_xor_sync(0xffffffffu, s, o);
            if (l == 0) sSP[w] = s;
        }
        __syncthreads();
        // pass 2: negative-branch partials  sN = sum_{att2<=key} F2n
        #pragma unroll
        for (int r = 0; r < RP_ROWS; r++) {
            float key = skey[r];
            float p = ((tv.x > key) ? 0.f : nv.x)
                    + ((tv.y > key) ? 0.f : nv.y)
                    + ((tv.z > key) ? 0.f : nv.z)
                    + ((tv.w > key) ? 0.f : nv.w);
            sh.red[r * 512 + tid] = p;
        }
        __syncthreads();
        {
            int w = tid >> 5, l = tid & 31;
            float s = 0.f;
            #pragma unroll
            for (int i = 0; i < 16; i++) s += sh.red[w * 512 + l + 32 * i];
            #pragma unroll
            for (int o = 16; o > 0; o >>= 1) s += __shfl_xor_sync(0xffffffffu, s, o);
            if (l == 0) {
                int row = row0 + w;
                float E1p = g_E1p[row], E1n = g_E1n[row];
                float S = E1p * sSP[w] + E1n * s;        // correct two-branch S
                float invS = 1.f / S;
                float c1v = E1p * invS, c2v = E1n * invS;
                sc1[w] = c1v; sc2[w] = c2v;
                g_c1[row] = c1v; g_c2[row] = c2v;
            }
        }
        __syncthreads();
        // probs stores (streaming)
        #pragma unroll
        for (int r = 0; r < RP_ROWS; r++) {
            int row = row0 + r;
            float key = skey[r], c1 = sc1[r], c2 = sc2[r];
            float4 o;
            o.x = (tv.x > key) ? c1 * pv.x : c2 * nv.x;
            o.y = (tv.y > key) ? c1 * pv.y : c2 * nv.y;
            o.z = (tv.z > key) ? c1 * pv.z : c2 * nv.z;
            o.w = (tv.w > key) ? c1 * pv.w : c2 * nv.w;
            __stcs((float4*)(out_p + (size_t)row * MM) + tid, o);
        }
        return;
    }

    // ---- vector-scan path: spin on sort flag, then 4 chunks per block ----
    int sid = blockIdx.x - (SORT_BLOCKS + PROB_BLOCKS);   // 0..255
    int b  = sid >> 5;
    int cg = sid & 31;
    int sub = tid >> 7;
    int e   = tid & 127;
    int c   = cg * 4 + sub;
    if (tid == 0) {
        while (((volatile int*)g_flag)[b] == 0) {}
    }
    __syncthreads();
    __threadfence();
    if (tid < 64) {
        int cc = tid >> 4, j = tid & 15;
        sh.scan.smi[cc][j] = g_sortidx[b * MM + (cg * 4 + cc) * CHUNK + j];
    }
    __syncthreads();
    #pragma unroll
    for (int i = tid; i < 4 * CHUNK * 32; i += 512) {
        int cc = i >> 9, row = (i >> 5) & 15, c4 = i & 31;
        ((float4*)&sh.scan.sw[cc][row][0])[c4] =
            ((const float4*)(g_Wh2 + (size_t)(b * MM + sh.scan.smi[cc][row]) * EE))[c4];
    }
    if (tid < 64) {
        int cc = tid >> 4, j = tid & 15;
        sh.scan.sfp[cc][j] = g_F2p[b * MM + sh.scan.smi[cc][j]];
        sh.scan.sfn[cc][j] = g_F2n[b * MM + sh.scan.smi[cc][j]];
    }
    __syncthreads();
    {
        float runN = 0.f;
        #pragma unroll
        for (int j = 0; j < CHUNK; j++) {
            g_preN[((size_t)b * (MM + 1) + c * CHUNK + j) * EE + e] = runN;
            runN += sh.scan.sfn[sub][j] * sh.scan.sw[sub][j][e];
        }
        g_chN[(b * NCHUNK + c) * EE + e] = runN;
    }
    {
        float runP = 0.f;
        #pragma unroll
        for (int j = CHUNK - 1; j >= 0; j--) {
            runP += sh.scan.sfp[sub][j] * sh.scan.sw[sub][j][e];
            g_sufP[((size_t)b * (MM + 1) + c * CHUNK + j) * EE + e] = runP;
        }
        g_chP[(b * NCHUNK + c) * EE + e] = runP;
    }
}

// ---------------- 4. chunk offsets: block-parallel Hillis-Steele (256 blocks) -------
// Each 512-thread block = 4 scan groups; group handles one (b, e) pair over 128 chunks.
__global__ void __launch_bounds__(512) k_offsets() {
    __shared__ float sN[512], sP[512];
    int gid = blockIdx.x;          // 0..255
    int b  = gid >> 5;             // 32 blocks per batch
    int eg = gid & 31;             // e-group of 4
    int grp = threadIdx.x >> 7;    // 0..3
    int c   = threadIdx.x & 127;   // chunk index
    int e   = eg * 4 + grp;
    int base = grp * 128;

    float vN = g_chN[(b * NCHUNK + c) * EE + e];
    float vP = g_chP[(b * NCHUNK + c) * EE + e];
    sN[base + c] = vN;
    sP[base + (127 - c)] = vP;     // reversed image for suffix scan
    __syncthreads();
    #pragma unroll
    for (int s = 1; s < 128; s <<= 1) {
        float tn = (c >= s) ? sN[base + c - s] : 0.f;
        float tp = (c >= s) ? sP[base + c - s] : 0.f;
        __syncthreads();
        sN[base + c] += tn;
        sP[base + c] += tp;
        __syncthreads();
    }
    // exclusive prefix N: incl[c-1] (0 at c=0)
    float exN = (c > 0) ? sN[base + c - 1] : 0.f;
    g_offN[(b * (NCHUNK + 1) + c) * EE + e] = exN;
    // exclusive suffix P: reversed incl at (127-c)-1 (0 at c=127)
    float exP = (c < 127) ? sP[base + (127 - c) - 1] : 0.f;
    g_offP[(b * (NCHUNK + 1) + c) * EE + e] = exP;
    if (c == 127) {
        g_offN[(b * (NCHUNK + 1) + NCHUNK) * EE + e] = sN[base + 127];  // total
    }
    if (c == 0) {
        g_offP[(b * (NCHUNK + 1) + NCHUNK) * EE + e] = 0.f;
        // zero local sentinels at k = MM
        g_preN[((size_t)b * (MM + 1) + MM) * EE + e] = 0.f;
        g_sufP[((size_t)b * (MM + 1) + MM) * EE + e] = 0.f;
    }
}

// ---------------- 5. context: binary search + compose local+offset vectors ----------
__global__ void __launch_bounds__(512) k_ctx(float* __restrict__ out_ctx) {
    __shared__ int   slo[RP_ROWS];
    __shared__ float sc1[RP_ROWS], sc2[RP_ROWS];
    int g = blockIdx.x;
    int row0 = g * RP_ROWS;
    int b = row0 >> 11;
    int tid = threadIdx.x;
    if (tid < RP_ROWS) {
        int row = row0 + tid;
        float key = g_key[row];
        const float* sv = g_sortv + b * MM;
        int lo = 0, hi = MM;
        while (lo < hi) {
            int mid = (lo + hi) >> 1;
            if (sv[mid] > key) hi = mid; else lo = mid + 1;
        }
        slo[tid] = lo;
        sc1[tid] = g_c1[row];
        sc2[tid] = g_c2[row];
    }
    __syncthreads();
    int e  = tid & (EE - 1);
    int rb = tid >> 7;
    #pragma unroll
    for (int it = 0; it < RP_ROWS / 4; it++) {
        int r = it * 4 + rb;
        int row = row0 + r;
        int k = slo[r], c = k >> 4;
        float sufP = g_sufP[((size_t)b * (MM + 1) + k) * EE + e]
                   + g_offP[(b * (NCHUNK + 1) + c) * EE + e];
        float preN = g_preN[((size_t)b * (MM + 1) + k) * EE + e]
                   + g_offN[(b * (NCHUNK + 1) + c) * EE + e];
        out_ctx[(size_t)row * EE + e] = sc1[r] * sufP + sc2[r] * preN;
    }
}

// ---------------- launch ----------------
extern "C" void kernel_launch(void* const* d_in, const int* in_sizes, int n_in,
                              void* d_out, int out_size) {
    const float* in1  = (const float*)d_in[0];   // (8,2048,256)
    const float* in2  = (const float*)d_in[1];   // (8,2048,256)
    const float* mask = (const float*)d_in[2];   // (8,1,2048)
    const float* W1   = (const float*)d_in[3];   // (256,128)
    const float* a1   = (const float*)d_in[4];   // (256,1)
    float* out = (float*)d_out;
    float* out_ctx   = out;                              // (8,2048,128)
    float* out_probs = out + (size_t)BB * NN * EE;       // (8,2048,2048)

    k_v<<<1, 256>>>(W1, a1);                             // also resets g_flag
    k_wh2<<<GEMM_BLOCKS + ATT1_BLOCKS, 256>>>(in2, W1, mask, a1, in1);
    k_mega<<<MEGA_BLOCKS, 512>>>(out_probs);
    k_offsets<<<BB * 32, 512>>>();
    k_ctx<<<BB * NN / RP_ROWS, 512>>>(out_ctx);
}